// round 3
// baseline (speedup 1.0000x reference)
#include <cuda_runtime.h>
#include <cstddef>

// HaarDown: x (B=8, C=64, H=512, W=512) f32 -> out (B, C*3, H2=256, W2=256) f32
// 2x2 block [a b; c d]:
//   o0 = (a - b - c + d) * 0.5
//   o1 = (a - b + c - d) * 0.5
//   o2 = (a + b - c - d) * 0.5
// out channel = c*3 + k
//
// Persistent single-wave kernel: 1216 CTAs (152 SMs x 8 resident), grid-stride
// loop over 8.4M tiles. Eliminates ~27 wave transitions + CTA retire churn of
// the flat-grid version; memory pipeline stays continuously fed.

namespace {
constexpr int B  = 8;
constexpr int C  = 64;
constexpr int H  = 512;
constexpr int W  = 512;
constexpr int H2 = H / 2;   // 256
constexpr int W2 = W / 2;   // 256
constexpr int WG = W2 / 4;  // 64 groups of 4 output columns per row
constexpr int THREADS_PER_BLOCK = 256;
constexpr long long TOTAL_TILES = (long long)B * C * H2 * WG; // 8,388,608
constexpr int NUM_BLOCKS = 152 * 8;                           // 1216, single wave
}

__global__ __launch_bounds__(THREADS_PER_BLOCK, 8)
void haar_down_kernel(const float* __restrict__ x, float* __restrict__ out) {
    const int stride = NUM_BLOCKS * THREADS_PER_BLOCK;          // 311,296
    constexpr int TOTAL = (int)TOTAL_TILES;

    for (int tid = blockIdx.x * THREADS_PER_BLOCK + threadIdx.x;
         tid < TOTAL; tid += stride) {

        int wg = tid & (WG - 1);           // group of 4 output columns
        int h2 = (tid >> 6) & (H2 - 1);    // output row
        int bc = tid >> 14;                // fused (b, c): 0..511

        const float* p0 = x + (size_t)bc * (H * W) + (size_t)(2 * h2) * W + wg * 8;
        const float4 r0a = __ldg((const float4*)(p0));
        const float4 r0b = __ldg((const float4*)(p0 + 4));
        const float4 r1a = __ldg((const float4*)(p0 + W));
        const float4 r1b = __ldg((const float4*)(p0 + W + 4));

        float4 o0, o1, o2;
        {
            float amb = r0a.x - r0a.y, apb = r0a.x + r0a.y;
            float cmd = r1a.x - r1a.y, cpd = r1a.x + r1a.y;
            o0.x = (amb - cmd) * 0.5f;
            o1.x = (amb + cmd) * 0.5f;
            o2.x = (apb - cpd) * 0.5f;
        }
        {
            float amb = r0a.z - r0a.w, apb = r0a.z + r0a.w;
            float cmd = r1a.z - r1a.w, cpd = r1a.z + r1a.w;
            o0.y = (amb - cmd) * 0.5f;
            o1.y = (amb + cmd) * 0.5f;
            o2.y = (apb - cpd) * 0.5f;
        }
        {
            float amb = r0b.x - r0b.y, apb = r0b.x + r0b.y;
            float cmd = r1b.x - r1b.y, cpd = r1b.x + r1b.y;
            o0.z = (amb - cmd) * 0.5f;
            o1.z = (amb + cmd) * 0.5f;
            o2.z = (apb - cpd) * 0.5f;
        }
        {
            float amb = r0b.z - r0b.w, apb = r0b.z + r0b.w;
            float cmd = r1b.z - r1b.w, cpd = r1b.z + r1b.w;
            o0.w = (amb - cmd) * 0.5f;
            o1.w = (amb + cmd) * 0.5f;
            o2.w = (apb - cpd) * 0.5f;
        }

        int b = bc >> 6;          // / 64
        int c = bc & 63;          // % 64
        constexpr int PLANE = H2 * W2; // 65536
        float* obase = out + ((size_t)(b * (C * 3) + c * 3) * PLANE)
                           + (size_t)h2 * W2 + wg * 4;

        *((float4*)(obase))             = o0;
        *((float4*)(obase + PLANE))     = o1;
        *((float4*)(obase + 2 * PLANE)) = o2;
    }
}

extern "C" void kernel_launch(void* const* d_in, const int* in_sizes, int n_in,
                              void* d_out, int out_size) {
    const float* x = (const float*)d_in[0];
    float* out = (float*)d_out;
    haar_down_kernel<<<NUM_BLOCKS, THREADS_PER_BLOCK>>>(x, out);
}

// round 4
// speedup vs baseline: 1.1136x; 1.1136x over previous
#include <cuda_runtime.h>
#include <cstddef>

// HaarDown: x (B=8, C=64, H=512, W=512) f32 -> out (B, C*3, H2=256, W2=256) f32
// 2x2 block [a b; c d]:
//   o0 = (a - b - c + d) * 0.5
//   o1 = (a - b + c - d) * 0.5
//   o2 = (a + b - c - d) * 0.5
// out channel = c*3 + k
//
// Flat grid, 2 output row-pairs per thread: 8 independent front-batched
// LDG.128 (MLP_p1 = 8, 128B in flight per thread), 6 STG.128.

namespace {
constexpr int B  = 8;
constexpr int C  = 64;
constexpr int H  = 512;
constexpr int W  = 512;
constexpr int H2 = H / 2;    // 256
constexpr int W2 = W / 2;    // 256
constexpr int WG = W2 / 4;   // 64 groups of 4 output columns per row
constexpr int HP = H2 / 2;   // 128 row-pairs of output rows
constexpr int THREADS_PER_BLOCK = 256;
constexpr long long TOTAL_THREADS = (long long)B * C * HP * WG; // 4,194,304
constexpr int NUM_BLOCKS = (int)(TOTAL_THREADS / THREADS_PER_BLOCK); // 16384
}

__device__ __forceinline__ void haar4(const float4 ra, const float4 rb,
                                      float4& o0, float4& o1, float4& o2) {
    // column pairs: (ra.x,ra.y,rb.x,rb.y) and (ra.z,ra.w,rb.z,rb.w) etc.
    {
        float amb = ra.x - ra.y, apb = ra.x + ra.y;
        float cmd = rb.x - rb.y, cpd = rb.x + rb.y;
        o0.x = (amb - cmd) * 0.5f;
        o1.x = (amb + cmd) * 0.5f;
        o2.x = (apb - cpd) * 0.5f;
    }
    {
        float amb = ra.z - ra.w, apb = ra.z + ra.w;
        float cmd = rb.z - rb.w, cpd = rb.z + rb.w;
        o0.y = (amb - cmd) * 0.5f;
        o1.y = (amb + cmd) * 0.5f;
        o2.y = (apb - cpd) * 0.5f;
    }
}

__global__ __launch_bounds__(THREADS_PER_BLOCK)
void haar_down_kernel(const float* __restrict__ x, float* __restrict__ out) {
    int tid = blockIdx.x * THREADS_PER_BLOCK + threadIdx.x;

    int wg = tid & (WG - 1);            // group of 4 output columns
    int hp = (tid >> 6) & (HP - 1);     // output row-pair: rows 2*hp, 2*hp+1
    int bc = tid >> 13;                 // fused (b, c): 0..511

    // Input: 4 consecutive rows, 8 consecutive floats each.
    // Front-batch all 8 independent LDG.128 (MLP = 8).
    const float* p0 = x + (size_t)bc * (H * W) + (size_t)(4 * hp) * W + wg * 8;
    const float4 r0a = __ldg((const float4*)(p0));
    const float4 r0b = __ldg((const float4*)(p0 + 4));
    const float4 r1a = __ldg((const float4*)(p0 + W));
    const float4 r1b = __ldg((const float4*)(p0 + W + 4));
    const float4 r2a = __ldg((const float4*)(p0 + 2 * W));
    const float4 r2b = __ldg((const float4*)(p0 + 2 * W + 4));
    const float4 r3a = __ldg((const float4*)(p0 + 3 * W));
    const float4 r3b = __ldg((const float4*)(p0 + 3 * W + 4));

    // Row-pair 0 (output row 2*hp): rows r0, r1
    float4 p00, p01, p02, q00, q01, q02;
    haar4(r0a, r1a, p00, p01, p02);
    {
        float4 t0, t1, t2;
        haar4(r0b, r1b, t0, t1, t2);
        p00.z = t0.x; p00.w = t0.y;
        p01.z = t1.x; p01.w = t1.y;
        p02.z = t2.x; p02.w = t2.y;
    }
    // Row-pair 1 (output row 2*hp+1): rows r2, r3
    haar4(r2a, r3a, q00, q01, q02);
    {
        float4 t0, t1, t2;
        haar4(r2b, r3b, t0, t1, t2);
        q00.z = t0.x; q00.w = t0.y;
        q01.z = t1.x; q01.w = t1.y;
        q02.z = t2.x; q02.w = t2.y;
    }

    int b = bc >> 6;          // / 64
    int c = bc & 63;          // % 64
    constexpr int PLANE = H2 * W2; // 65536
    float* obase = out + ((size_t)(b * (C * 3) + c * 3) * PLANE)
                       + (size_t)(2 * hp) * W2 + wg * 4;

    *((float4*)(obase))                  = p00;
    *((float4*)(obase + W2))             = q00;
    *((float4*)(obase + PLANE))          = p01;
    *((float4*)(obase + PLANE + W2))     = q01;
    *((float4*)(obase + 2 * PLANE))      = p02;
    *((float4*)(obase + 2 * PLANE + W2)) = q02;
}

extern "C" void kernel_launch(void* const* d_in, const int* in_sizes, int n_in,
                              void* d_out, int out_size) {
    const float* x = (const float*)d_in[0];
    float* out = (float*)d_out;
    haar_down_kernel<<<NUM_BLOCKS, THREADS_PER_BLOCK>>>(x, out);
}

// round 5
// speedup vs baseline: 1.1198x; 1.0056x over previous
#include <cuda_runtime.h>
#include <cstddef>

// HaarDown: x (B=8, C=64, H=512, W=512) f32 -> out (B, C*3, H2=256, W2=256) f32
// 2x2 block [a b; c d]:
//   o0 = (a - b - c + d) * 0.5
//   o1 = (a - b + c - d) * 0.5
//   o2 = (a + b - c - d) * 0.5
// out channel = c*3 + k
//
// HBM-roofline streaming kernel (measured at ~6.88 TB/s = mixed R/W ceiling).
// 256-bit vector ld/st, flat grid, 512-thread blocks.

namespace {
constexpr int B  = 8;
constexpr int C  = 64;
constexpr int H  = 512;
constexpr int W  = 512;
constexpr int H2 = H / 2;   // 256
constexpr int W2 = W / 2;   // 256
constexpr int WG = W2 / 8;  // 32 groups of 8 output columns per row
constexpr int THREADS_PER_BLOCK = 512;
constexpr long long TOTAL_THREADS = (long long)B * C * H2 * WG; // 4,194,304
constexpr int NUM_BLOCKS = (int)(TOTAL_THREADS / THREADS_PER_BLOCK); // 8192
}

__device__ __forceinline__ void ldg256_nc(const float* p, float v[8]) {
    asm volatile(
        "ld.global.nc.v8.f32 {%0,%1,%2,%3,%4,%5,%6,%7}, [%8];"
        : "=f"(v[0]), "=f"(v[1]), "=f"(v[2]), "=f"(v[3]),
          "=f"(v[4]), "=f"(v[5]), "=f"(v[6]), "=f"(v[7])
        : "l"(p));
}

__device__ __forceinline__ void stg256_cs(float* p, const float v[8]) {
    asm volatile(
        "st.global.cs.v8.f32 [%0], {%1,%2,%3,%4,%5,%6,%7,%8};"
        :: "l"(p),
           "f"(v[0]), "f"(v[1]), "f"(v[2]), "f"(v[3]),
           "f"(v[4]), "f"(v[5]), "f"(v[6]), "f"(v[7])
        : "memory");
}

__global__ __launch_bounds__(THREADS_PER_BLOCK)
void haar_down_kernel(const float* __restrict__ x, float* __restrict__ out) {
    int tid = blockIdx.x * THREADS_PER_BLOCK + threadIdx.x;

    int wg = tid & (WG - 1);           // group of 8 output columns
    int h2 = (tid >> 5) & (H2 - 1);    // output row
    int bc = tid >> 13;                // fused (b, c): 0..511

    // Input: two rows of 16 consecutive floats (covers 8 output columns).
    // Front-batch all 4 independent 256-bit loads (128B in flight).
    const float* p0 = x + (size_t)bc * (H * W) + (size_t)(2 * h2) * W + wg * 16;
    float r0[16], r1[16];
    ldg256_nc(p0,          r0);
    ldg256_nc(p0 + 8,      r0 + 8);
    ldg256_nc(p0 + W,      r1);
    ldg256_nc(p0 + W + 8,  r1 + 8);

    float o0[8], o1[8], o2[8];
    #pragma unroll
    for (int j = 0; j < 8; j++) {
        float a = r0[2 * j], b = r0[2 * j + 1];
        float c = r1[2 * j], d = r1[2 * j + 1];
        float amb = a - b;
        float apb = a + b;
        float cmd = c - d;
        float cpd = c + d;
        o0[j] = (amb - cmd) * 0.5f;   // a-b-c+d
        o1[j] = (amb + cmd) * 0.5f;   // a-b+c-d
        o2[j] = (apb - cpd) * 0.5f;   // a+b-c-d
    }

    // Output: channel = c*3 + k, bc = b*C + c
    int b = bc >> 6;          // / 64
    int c = bc & 63;          // % 64
    constexpr int PLANE = H2 * W2; // 65536
    float* obase = out + ((size_t)(b * (C * 3) + c * 3) * PLANE)
                       + (size_t)h2 * W2 + wg * 8;

    stg256_cs(obase,             o0);
    stg256_cs(obase + PLANE,     o1);
    stg256_cs(obase + 2 * PLANE, o2);
}

extern "C" void kernel_launch(void* const* d_in, const int* in_sizes, int n_in,
                              void* d_out, int out_size) {
    const float* x = (const float*)d_in[0];
    float* out = (float*)d_out;
    haar_down_kernel<<<NUM_BLOCKS, THREADS_PER_BLOCK>>>(x, out);
}